// round 5
// baseline (speedup 1.0000x reference)
#include <cuda_runtime.h>
#include <cuda_bf16.h>
#include <cstdint>

// ---------------------------------------------------------------------------
// DeepFM forward — HMMA bf16 3-term split GEMMs, double-buffered cp.async,
// col-stats fused into GEMM epilogues.
//   B=16384, F=26, D=32, DIN=832, H1=256, H2=128, V=100000
// Pipeline:
//   zero_stats; prep_w; gather_fm; gemm_mma<832,256> (+stats1);
//   bn_prep; act; gemm_mma<256,128> (+stats2); final.
// ---------------------------------------------------------------------------

#define BATCH  16384
#define NF     26
#define ED     32
#define DIN    832
#define H1N    256
#define H2N    128
#define VOCAB  100000
#define BN_EPS 1e-5f

// ---- scratch ---------------------------------------------------------------
__device__ unsigned short g_Xh[(size_t)BATCH * DIN];
__device__ unsigned short g_Xl[(size_t)BATCH * DIN];
__device__ float          g_H1[(size_t)BATCH * H1N];
__device__ unsigned short g_A2h[(size_t)BATCH * H1N];
__device__ unsigned short g_A2l[(size_t)BATCH * H1N];
__device__ float          g_H2[(size_t)BATCH * H2N];
__device__ unsigned short g_W1Th[H1N * DIN], g_W1Tl[H1N * DIN];
__device__ unsigned short g_W2Th[H2N * H1N], g_W2Tl[H2N * H1N];
__device__ float g_fm[BATCH];
__device__ float g_stats1[2 * H1N];
__device__ float g_stats2[2 * H2N];
__device__ float g_sc1[H1N], g_sh1[H1N];

// ---- PTX helpers -----------------------------------------------------------
__device__ __forceinline__ uint32_t smem_u32(const void* p) {
    uint32_t a;
    asm("{ .reg .u64 t; cvta.to.shared.u64 t, %1; cvt.u32.u64 %0, t; }"
        : "=r"(a) : "l"(p));
    return a;
}
__device__ __forceinline__ void cp16(uint32_t dst, const void* src) {
    asm volatile("cp.async.cg.shared.global [%0], [%1], 16;"
                 :: "r"(dst), "l"(src));
}
#define CP_COMMIT() asm volatile("cp.async.commit_group;" ::: "memory")

__device__ __forceinline__ void ldsm4(uint32_t* r, uint32_t addr) {
    asm volatile("ldmatrix.sync.aligned.m8n8.x4.shared.b16 {%0,%1,%2,%3}, [%4];"
                 : "=r"(r[0]), "=r"(r[1]), "=r"(r[2]), "=r"(r[3]) : "r"(addr));
}
__device__ __forceinline__ void mma16816(float* d, const uint32_t* a,
                                         const uint32_t* b) {
    asm volatile(
        "mma.sync.aligned.m16n8k16.row.col.f32.bf16.bf16.f32 "
        "{%0,%1,%2,%3}, {%4,%5,%6,%7}, {%8,%9}, {%0,%1,%2,%3};"
        : "+f"(d[0]), "+f"(d[1]), "+f"(d[2]), "+f"(d[3])
        : "r"(a[0]), "r"(a[1]), "r"(a[2]), "r"(a[3]), "r"(b[0]), "r"(b[1]));
}

// ---- tiny kernels ----------------------------------------------------------
__global__ void zero_stats_k() {
    int t = threadIdx.x;
    g_stats1[t] = 0.f; g_stats1[H1N + t] = 0.f;
    if (t < H2N) { g_stats2[t] = 0.f; g_stats2[H2N + t] = 0.f; }
}

__global__ void prep_w_k(const float* __restrict__ W1, const float* __restrict__ W2) {
    const int t1 = DIN * H1N;
    const int tot = t1 + H1N * H2N;
    for (int i = blockIdx.x * blockDim.x + threadIdx.x; i < tot;
         i += gridDim.x * blockDim.x) {
        if (i < t1) {
            int k = i / H1N, n = i % H1N;
            float v = W1[i];
            __nv_bfloat16 h = __float2bfloat16(v);
            __nv_bfloat16 l = __float2bfloat16(v - __bfloat162float(h));
            g_W1Th[n * DIN + k] = __bfloat16_as_ushort(h);
            g_W1Tl[n * DIN + k] = __bfloat16_as_ushort(l);
        } else {
            int j = i - t1;
            int k = j / H2N, n = j % H2N;
            float v = W2[j];
            __nv_bfloat16 h = __float2bfloat16(v);
            __nv_bfloat16 l = __float2bfloat16(v - __bfloat162float(h));
            g_W2Th[n * H1N + k] = __bfloat16_as_ushort(h);
            g_W2Tl[n * H1N + k] = __bfloat16_as_ushort(l);
        }
    }
}

__global__ void gather_fm_k(const int* __restrict__ xc,
                            const float* __restrict__ lin_tab,
                            const float* __restrict__ lat_tab,
                            const float* __restrict__ bias) {
    int row  = blockIdx.x * 8 + (threadIdx.x >> 5);
    int lane = threadIdx.x & 31;

    int   idx  = 0;
    float linv = 0.f;
    if (lane < NF) {
        idx  = xc[row * NF + lane];
        linv = lin_tab[lane * VOCAB + idx];
    }
    float sdim = 0.f, sq = 0.f;
    unsigned short* xh = &g_Xh[(size_t)row * DIN];
    unsigned short* xl = &g_Xl[(size_t)row * DIN];
#pragma unroll
    for (int f = 0; f < NF; ++f) {
        int id = __shfl_sync(0xffffffffu, idx, f);
        float e = lat_tab[((size_t)f * VOCAB + id) * ED + lane];
        __nv_bfloat16 h = __float2bfloat16(e);
        __nv_bfloat16 l = __float2bfloat16(e - __bfloat162float(h));
        xh[f * ED + lane] = __bfloat16_as_ushort(h);
        xl[f * ED + lane] = __bfloat16_as_ushort(l);
        sdim += e; sq += e * e;
    }
    float t = sdim * sdim - sq;
#pragma unroll
    for (int o = 16; o; o >>= 1) {
        t    += __shfl_xor_sync(0xffffffffu, t, o);
        linv += __shfl_xor_sync(0xffffffffu, linv, o);
    }
    if (lane == 0) g_fm[row] = linv + 0.5f * t + bias[0];
}

// ---- HMMA GEMM, double-buffered, stats fused -------------------------------
// C[B x NCOLS] = A[B x KTOT] @ Bt[NCOLS x KTOT]^T + bias; also accumulates
// per-column sum / sumsq of C into stats[0..NCOLS) / stats[NCOLS..2*NCOLS).
// SMEM: 2 stages x 4 arrays x 128 rows x 40 halves (80B row, pad 8).
template<int KTOT, int NCOLS>
__global__ __launch_bounds__(256, 2)
void gemm_mma(const unsigned short* __restrict__ Ah,
              const unsigned short* __restrict__ Al,
              const unsigned short* __restrict__ Bh,
              const unsigned short* __restrict__ Bl,
              const float* __restrict__ bias, float* __restrict__ C,
              float* __restrict__ stats) {
    extern __shared__ char smem[];
    constexpr int STR   = 40;                 // halves per row
    constexpr int TILE  = 128 * STR * 2;      // 10240 B per array
    constexpr int STAGE = 4 * TILE;           // 40960 B
    constexpr int NCHUNK = KTOT / 32;
    __shared__ float csum[128], csq[128];

    const uint32_t sb = smem_u32(smem);
    const int tid = threadIdx.x;
    const int lane = tid & 31;
    const int wid = tid >> 5;
    const int warp_m = wid & 3;
    const int warp_n = wid >> 2;
    const int rowBase = blockIdx.x * 128;
    const int colBase = blockIdx.y * 128;

    float acc[2][8][4];
#pragma unroll
    for (int i = 0; i < 2; ++i)
#pragma unroll
        for (int j = 0; j < 8; ++j)
#pragma unroll
            for (int k = 0; k < 4; ++k) acc[i][j][k] = 0.f;

    const int a_row = warp_m * 32 + (lane & 15);
    const int a_col8 = (lane >> 4) << 3;
    const int b_row_base = warp_n * 64 + (lane & 7) + ((lane >> 4) << 3);
    const int b_col8 = ((lane >> 3) & 1) << 3;

    const int ld_row = tid >> 2;              // 0..63
    const int ld_seg = tid & 3;               // 0..3

    auto load_stage = [&](int s, int kc) {
        uint32_t base = sb + s * STAGE;
#pragma unroll
        for (int p = 0; p < 2; ++p) {
            int row = p * 64 + ld_row;
            uint32_t soff = (uint32_t)(row * STR + ld_seg * 8) * 2;
            size_t ga = (size_t)(rowBase + row) * KTOT + kc * 32 + ld_seg * 8;
            size_t gb = (size_t)(colBase + row) * KTOT + kc * 32 + ld_seg * 8;
            cp16(base + soff,            Ah + ga);
            cp16(base + TILE + soff,     Al + ga);
            cp16(base + 2 * TILE + soff, Bh + gb);
            cp16(base + 3 * TILE + soff, Bl + gb);
        }
        CP_COMMIT();
    };

    load_stage(0, 0);

    for (int kc = 0; kc < NCHUNK; ++kc) {
        const int cur = kc & 1;
        if (kc + 1 < NCHUNK) {
            load_stage(cur ^ 1, kc + 1);
            asm volatile("cp.async.wait_group 1;" ::: "memory");
        } else {
            asm volatile("cp.async.wait_group 0;" ::: "memory");
        }
        __syncthreads();

        const uint32_t base = sb + cur * STAGE;
#pragma unroll
        for (int ks = 0; ks < 2; ++ks) {
            uint32_t ah[2][4], al[2][4];
#pragma unroll
            for (int mt = 0; mt < 2; ++mt) {
                uint32_t off = (uint32_t)((a_row + mt * 16) * STR +
                                          ks * 16 + a_col8) * 2;
                ldsm4(ah[mt], base + off);
                ldsm4(al[mt], base + TILE + off);
            }
#pragma unroll
            for (int nb = 0; nb < 4; ++nb) {
                uint32_t bh[4], bl[4];
                uint32_t off = (uint32_t)((b_row_base + nb * 16) * STR +
                                          ks * 16 + b_col8) * 2;
                ldsm4(bh, base + 2 * TILE + off);
                ldsm4(bl, base + 3 * TILE + off);
#pragma unroll
                for (int mt = 0; mt < 2; ++mt) {
                    mma16816(acc[mt][2 * nb],     ah[mt], bh);
                    mma16816(acc[mt][2 * nb],     ah[mt], bl);
                    mma16816(acc[mt][2 * nb],     al[mt], bh);
                    mma16816(acc[mt][2 * nb + 1], ah[mt], bh + 2);
                    mma16816(acc[mt][2 * nb + 1], ah[mt], bl + 2);
                    mma16816(acc[mt][2 * nb + 1], al[mt], bh + 2);
                }
            }
        }
        __syncthreads();
    }

    // ---- epilogue: bias add, store, fused column stats ----
    if (tid < 128) { csum[tid] = 0.f; csq[tid] = 0.f; }
    __syncthreads();

#pragma unroll
    for (int nt = 0; nt < 8; ++nt) {
        int cl = warp_n * 64 + nt * 8 + 2 * (lane & 3);   // 0..127 in tile
        int c  = colBase + cl;
        float2 bv = *(const float2*)&bias[c];
        float s0 = 0.f, s1 = 0.f, q0 = 0.f, q1 = 0.f;
#pragma unroll
        for (int mt = 0; mt < 2; ++mt) {
            int r0 = rowBase + warp_m * 32 + mt * 16 + (lane >> 2);
            float2 v0 = {acc[mt][nt][0] + bv.x, acc[mt][nt][1] + bv.y};
            float2 v1 = {acc[mt][nt][2] + bv.x, acc[mt][nt][3] + bv.y};
            *(float2*)&C[(size_t)r0 * NCOLS + c]       = v0;
            *(float2*)&C[(size_t)(r0 + 8) * NCOLS + c] = v1;
            s0 += v0.x + v1.x;  s1 += v0.y + v1.y;
            q0 += v0.x * v0.x + v1.x * v1.x;
            q1 += v0.y * v0.y + v1.y * v1.y;
        }
        atomicAdd(&csum[cl], s0);     atomicAdd(&csum[cl + 1], s1);
        atomicAdd(&csq[cl],  q0);     atomicAdd(&csq[cl + 1],  q1);
    }
    __syncthreads();
    if (tid < 128) {
        atomicAdd(&stats[colBase + tid],        csum[tid]);
        atomicAdd(&stats[NCOLS + colBase + tid], csq[tid]);
    }
}

// ---- BN prep, activation, final --------------------------------------------
__global__ void bn_prep_k(const float* __restrict__ g, const float* __restrict__ be) {
    int c = threadIdx.x;
    float s  = g_stats1[c];
    float sq = g_stats1[H1N + c];
    float mean = s * (1.f / BATCH);
    float var  = sq * (1.f / BATCH) - mean * mean;
    float rstd = rsqrtf(var + BN_EPS);
    float scl  = g[c] * rstd;
    g_sc1[c] = scl;
    g_sh1[c] = be[c] - mean * scl;
}

__global__ void act_k() {
    int q = blockIdx.x * blockDim.x + threadIdx.x;
    float4 v = ((const float4*)g_H1)[q];
    int c = (q * 4) & (H1N - 1);
    float h0 = fmaxf(fmaf(v.x, g_sc1[c + 0], g_sh1[c + 0]), 0.f);
    float h1 = fmaxf(fmaf(v.y, g_sc1[c + 1], g_sh1[c + 1]), 0.f);
    float h2 = fmaxf(fmaf(v.z, g_sc1[c + 2], g_sh1[c + 2]), 0.f);
    float h3 = fmaxf(fmaf(v.w, g_sc1[c + 3], g_sh1[c + 3]), 0.f);
    __nv_bfloat162 a = __floats2bfloat162_rn(h0, h1);
    __nv_bfloat162 b = __floats2bfloat162_rn(h2, h3);
    float l0 = h0 - __bfloat162float(a.x), l1 = h1 - __bfloat162float(a.y);
    float l2 = h2 - __bfloat162float(b.x), l3 = h3 - __bfloat162float(b.y);
    __nv_bfloat162 la = __floats2bfloat162_rn(l0, l1);
    __nv_bfloat162 lb = __floats2bfloat162_rn(l2, l3);
    uint2 uh = {*(uint32_t*)&a, *(uint32_t*)&b};
    uint2 ul = {*(uint32_t*)&la, *(uint32_t*)&lb};
    ((uint2*)g_A2h)[q] = uh;
    ((uint2*)g_A2l)[q] = ul;
}

__global__ void final_k(const float* __restrict__ W3, const float* __restrict__ b3,
                        const float* __restrict__ g2, const float* __restrict__ be2,
                        float* __restrict__ out) {
    __shared__ float sc[H2N], sh[H2N], w3s[H2N];
    int tid = threadIdx.x;
    if (tid < H2N) {
        float s  = g_stats2[tid];
        float sq = g_stats2[H2N + tid];
        float mean = s * (1.f / BATCH);
        float var  = sq * (1.f / BATCH) - mean * mean;
        float rstd = rsqrtf(var + BN_EPS);
        float scl  = g2[tid] * rstd;
        sc[tid] = scl;
        sh[tid] = be2[tid] - mean * scl;
        w3s[tid] = W3[tid];
    }
    __syncthreads();
    int warp = tid >> 5, lane = tid & 31;
    int row = blockIdx.x * 8 + warp;
    float acc = 0.f;
#pragma unroll
    for (int j = 0; j < 4; ++j) {
        int c = lane + j * 32;
        float v = g_H2[(size_t)row * H2N + c];
        acc += fmaxf(fmaf(v, sc[c], sh[c]), 0.f) * w3s[c];
    }
#pragma unroll
    for (int o = 16; o; o >>= 1) acc += __shfl_xor_sync(0xffffffffu, acc, o);
    if (lane == 0) out[row] = g_fm[row] + acc + b3[0];
}

// ---------------------------------------------------------------------------
extern "C" void kernel_launch(void* const* d_in, const int* in_sizes, int n_in,
                              void* d_out, int out_size) {
    const int*   xc   = (const int*)  d_in[0];
    const float* lin  = (const float*)d_in[1];
    const float* lat  = (const float*)d_in[2];
    const float* W1   = (const float*)d_in[3];
    const float* b1   = (const float*)d_in[4];
    const float* g1   = (const float*)d_in[5];
    const float* be1  = (const float*)d_in[6];
    const float* W2   = (const float*)d_in[7];
    const float* b2   = (const float*)d_in[8];
    const float* g2   = (const float*)d_in[9];
    const float* be2  = (const float*)d_in[10];
    const float* W3   = (const float*)d_in[11];
    const float* b3   = (const float*)d_in[12];
    const float* bias = (const float*)d_in[13];
    float* out = (float*)d_out;

    unsigned short *pXh, *pXl, *pA2h, *pA2l, *pW1h, *pW1l, *pW2h, *pW2l;
    float *pH1, *pH2, *pS1, *pS2;
    cudaGetSymbolAddress((void**)&pXh,  g_Xh);
    cudaGetSymbolAddress((void**)&pXl,  g_Xl);
    cudaGetSymbolAddress((void**)&pA2h, g_A2h);
    cudaGetSymbolAddress((void**)&pA2l, g_A2l);
    cudaGetSymbolAddress((void**)&pW1h, g_W1Th);
    cudaGetSymbolAddress((void**)&pW1l, g_W1Tl);
    cudaGetSymbolAddress((void**)&pW2h, g_W2Th);
    cudaGetSymbolAddress((void**)&pW2l, g_W2Tl);
    cudaGetSymbolAddress((void**)&pH1,  g_H1);
    cudaGetSymbolAddress((void**)&pH2,  g_H2);
    cudaGetSymbolAddress((void**)&pS1,  g_stats1);
    cudaGetSymbolAddress((void**)&pS2,  g_stats2);

    constexpr int SMEM = 2 * 4 * 128 * 40 * 2;   // 81920 bytes
    cudaFuncSetAttribute(gemm_mma<DIN, H1N>,
                         cudaFuncAttributeMaxDynamicSharedMemorySize, SMEM);
    cudaFuncSetAttribute(gemm_mma<H1N, H2N>,
                         cudaFuncAttributeMaxDynamicSharedMemorySize, SMEM);

    zero_stats_k<<<1, 256>>>();
    prep_w_k<<<480, 256>>>(W1, W2);
    gather_fm_k<<<BATCH / 8, 256>>>(xc, lin, lat, bias);
    gemm_mma<DIN, H1N><<<dim3(BATCH / 128, H1N / 128), 256, SMEM>>>(
        pXh, pXl, pW1h, pW1l, b1, pH1, pS1);
    bn_prep_k<<<1, H1N>>>(g1, be1);
    act_k<<<(BATCH * H1N / 4) / 256, 256>>>();
    gemm_mma<H1N, H2N><<<dim3(BATCH / 128, H2N / 128), 256, SMEM>>>(
        pA2h, pA2l, pW2h, pW2l, b2, pH2, pS2);
    final_k<<<BATCH / 8, 256>>>(W3, b3, g2, be2, out);
}

// round 6
// speedup vs baseline: 1.0918x; 1.0918x over previous
#include <cuda_runtime.h>
#include <cuda_bf16.h>
#include <cstdint>

// ---------------------------------------------------------------------------
// DeepFM forward — HMMA bf16 3-term split GEMMs.
// R6: k-chunk 64, TRUE 2-stage double buffer, full-N CTA tiles (128xN),
// 512 threads, 1 CTA/SM, grid = 128 = one wave. Stats fused in epilogue.
//   B=16384, F=26, D=32, DIN=832, H1=256, H2=128, V=100000
// ---------------------------------------------------------------------------

#define BATCH  16384
#define NF     26
#define ED     32
#define DIN    832
#define H1N    256
#define H2N    128
#define VOCAB  100000
#define BN_EPS 1e-5f

// ---- scratch ---------------------------------------------------------------
__device__ unsigned short g_Xh[(size_t)BATCH * DIN];
__device__ unsigned short g_Xl[(size_t)BATCH * DIN];
__device__ float          g_H1[(size_t)BATCH * H1N];
__device__ unsigned short g_A2h[(size_t)BATCH * H1N];
__device__ unsigned short g_A2l[(size_t)BATCH * H1N];
__device__ float          g_H2[(size_t)BATCH * H2N];
__device__ unsigned short g_W1Th[H1N * DIN], g_W1Tl[H1N * DIN];
__device__ unsigned short g_W2Th[H2N * H1N], g_W2Tl[H2N * H1N];
__device__ float g_fm[BATCH];
__device__ float g_stats1[2 * H1N];
__device__ float g_stats2[2 * H2N];
__device__ float g_sc1[H1N], g_sh1[H1N];

// ---- PTX helpers -----------------------------------------------------------
__device__ __forceinline__ uint32_t smem_u32(const void* p) {
    uint32_t a;
    asm("{ .reg .u64 t; cvta.to.shared.u64 t, %1; cvt.u32.u64 %0, t; }"
        : "=r"(a) : "l"(p));
    return a;
}
__device__ __forceinline__ void cp16(uint32_t dst, const void* src) {
    asm volatile("cp.async.cg.shared.global [%0], [%1], 16;"
                 :: "r"(dst), "l"(src));
}
#define CP_COMMIT() asm volatile("cp.async.commit_group;" ::: "memory")

__device__ __forceinline__ void ldsm4(uint32_t* r, uint32_t addr) {
    asm volatile("ldmatrix.sync.aligned.m8n8.x4.shared.b16 {%0,%1,%2,%3}, [%4];"
                 : "=r"(r[0]), "=r"(r[1]), "=r"(r[2]), "=r"(r[3]) : "r"(addr));
}
__device__ __forceinline__ void mma16816(float* d, const uint32_t* a,
                                         const uint32_t* b) {
    asm volatile(
        "mma.sync.aligned.m16n8k16.row.col.f32.bf16.bf16.f32 "
        "{%0,%1,%2,%3}, {%4,%5,%6,%7}, {%8,%9}, {%0,%1,%2,%3};"
        : "+f"(d[0]), "+f"(d[1]), "+f"(d[2]), "+f"(d[3])
        : "r"(a[0]), "r"(a[1]), "r"(a[2]), "r"(a[3]), "r"(b[0]), "r"(b[1]));
}

// ---- tiny kernels ----------------------------------------------------------
__global__ void zero_stats_k() {
    int t = threadIdx.x;
    g_stats1[t] = 0.f; g_stats1[H1N + t] = 0.f;
    if (t < H2N) { g_stats2[t] = 0.f; g_stats2[H2N + t] = 0.f; }
}

__global__ void prep_w_k(const float* __restrict__ W1, const float* __restrict__ W2) {
    const int t1 = DIN * H1N;
    const int tot = t1 + H1N * H2N;
    for (int i = blockIdx.x * blockDim.x + threadIdx.x; i < tot;
         i += gridDim.x * blockDim.x) {
        if (i < t1) {
            int k = i / H1N, n = i % H1N;
            float v = W1[i];
            __nv_bfloat16 h = __float2bfloat16(v);
            __nv_bfloat16 l = __float2bfloat16(v - __bfloat162float(h));
            g_W1Th[n * DIN + k] = __bfloat16_as_ushort(h);
            g_W1Tl[n * DIN + k] = __bfloat16_as_ushort(l);
        } else {
            int j = i - t1;
            int k = j / H2N, n = j % H2N;
            float v = W2[j];
            __nv_bfloat16 h = __float2bfloat16(v);
            __nv_bfloat16 l = __float2bfloat16(v - __bfloat162float(h));
            g_W2Th[n * H1N + k] = __bfloat16_as_ushort(h);
            g_W2Tl[n * H1N + k] = __bfloat16_as_ushort(l);
        }
    }
}

__global__ void gather_fm_k(const int* __restrict__ xc,
                            const float* __restrict__ lin_tab,
                            const float* __restrict__ lat_tab,
                            const float* __restrict__ bias) {
    int row  = blockIdx.x * 8 + (threadIdx.x >> 5);
    int lane = threadIdx.x & 31;

    int   idx  = 0;
    float linv = 0.f;
    if (lane < NF) {
        idx  = xc[row * NF + lane];
        linv = lin_tab[lane * VOCAB + idx];
    }
    float sdim = 0.f, sq = 0.f;
    unsigned short* xh = &g_Xh[(size_t)row * DIN];
    unsigned short* xl = &g_Xl[(size_t)row * DIN];
#pragma unroll
    for (int f = 0; f < NF; ++f) {
        int id = __shfl_sync(0xffffffffu, idx, f);
        float e = lat_tab[((size_t)f * VOCAB + id) * ED + lane];
        __nv_bfloat16 h = __float2bfloat16(e);
        __nv_bfloat16 l = __float2bfloat16(e - __bfloat162float(h));
        xh[f * ED + lane] = __bfloat16_as_ushort(h);
        xl[f * ED + lane] = __bfloat16_as_ushort(l);
        sdim += e; sq += e * e;
    }
    float t = sdim * sdim - sq;
#pragma unroll
    for (int o = 16; o; o >>= 1) {
        t    += __shfl_xor_sync(0xffffffffu, t, o);
        linv += __shfl_xor_sync(0xffffffffu, linv, o);
    }
    if (lane == 0) g_fm[row] = linv + 0.5f * t + bias[0];
}

// ---- HMMA GEMM, full-N tile, k-chunk 64, 2-stage double buffer -------------
// C[B x NCOLS] = A[B x KTOT] @ Bt[NCOLS x KTOT]^T + bias, fused col stats.
// 512 threads: 16 warps = 4m x 4n, warp tile 32 x (NCOLS/4).
// SMEM/stage: Ah,Al 128x72 halves + Bh,Bl NCOLS x 72 halves.
template<int KTOT, int NCOLS>
__global__ __launch_bounds__(512, 1)
void gemm_mma(const unsigned short* __restrict__ Ah,
              const unsigned short* __restrict__ Al,
              const unsigned short* __restrict__ Bh,
              const unsigned short* __restrict__ Bl,
              const float* __restrict__ bias, float* __restrict__ C,
              float* __restrict__ stats) {
    extern __shared__ char smem[];
    constexpr int STR    = 72;                    // halves per row (64 + 8 pad)
    constexpr int TILE_A = 128 * STR * 2;         // bytes
    constexpr int TILE_B = NCOLS * STR * 2;
    constexpr int STAGE  = 2 * TILE_A + 2 * TILE_B;
    constexpr int NCHUNK = KTOT / 64;
    constexpr int WN     = NCOLS / 4;             // warp n-tile
    constexpr int NB     = WN / 16;               // 16-col blocks per warp
    __shared__ float csum[NCOLS], csq[NCOLS];

    const uint32_t sb = smem_u32(smem);
    const int tid = threadIdx.x;
    const int lane = tid & 31;
    const int wid = tid >> 5;
    const int warp_m = wid & 3;
    const int warp_n = wid >> 2;
    const int rowBase = blockIdx.x * 128;

    float acc[2][NB * 2][4];
#pragma unroll
    for (int i = 0; i < 2; ++i)
#pragma unroll
        for (int j = 0; j < NB * 2; ++j)
#pragma unroll
            for (int k = 0; k < 4; ++k) acc[i][j][k] = 0.f;

    const int a_row = warp_m * 32 + (lane & 15);
    const int a_col8 = (lane >> 4) << 3;
    const int b_row_base = warp_n * WN + (lane & 7) + ((lane >> 4) << 3);
    const int b_col8 = ((lane >> 3) & 1) << 3;

    auto load_stage = [&](int s, int kc) {
        const uint32_t base = sb + s * STAGE;
#pragma unroll 2
        for (int i = tid; i < 128 * 8; i += 512) {
            int row = i >> 3, seg = i & 7;
            uint32_t soff = (uint32_t)(row * STR + seg * 8) * 2;
            size_t ga = (size_t)(rowBase + row) * KTOT + kc * 64 + seg * 8;
            cp16(base + soff,          Ah + ga);
            cp16(base + TILE_A + soff, Al + ga);
        }
#pragma unroll 2
        for (int i = tid; i < NCOLS * 8; i += 512) {
            int row = i >> 3, seg = i & 7;
            uint32_t soff = (uint32_t)(row * STR + seg * 8) * 2;
            size_t gb = (size_t)row * KTOT + kc * 64 + seg * 8;
            cp16(base + 2 * TILE_A + soff,          Bh + gb);
            cp16(base + 2 * TILE_A + TILE_B + soff, Bl + gb);
        }
        CP_COMMIT();
    };

    load_stage(0, 0);

    for (int kc = 0; kc < NCHUNK; ++kc) {
        const int cur = kc & 1;
        if (kc + 1 < NCHUNK) {
            load_stage(cur ^ 1, kc + 1);
            asm volatile("cp.async.wait_group 1;" ::: "memory");
        } else {
            asm volatile("cp.async.wait_group 0;" ::: "memory");
        }
        __syncthreads();

        const uint32_t base = sb + cur * STAGE;
#pragma unroll
        for (int ks = 0; ks < 4; ++ks) {
            uint32_t ah[2][4], al[2][4];
#pragma unroll
            for (int mt = 0; mt < 2; ++mt) {
                uint32_t off = (uint32_t)((a_row + mt * 16) * STR +
                                          ks * 16 + a_col8) * 2;
                ldsm4(ah[mt], base + off);
                ldsm4(al[mt], base + TILE_A + off);
            }
#pragma unroll
            for (int nb = 0; nb < NB; ++nb) {
                uint32_t bh[4], bl[4];
                uint32_t off = (uint32_t)((b_row_base + nb * 16) * STR +
                                          ks * 16 + b_col8) * 2;
                ldsm4(bh, base + 2 * TILE_A + off);
                ldsm4(bl, base + 2 * TILE_A + TILE_B + off);
#pragma unroll
                for (int mt = 0; mt < 2; ++mt) {
                    mma16816(acc[mt][2 * nb],     ah[mt], bh);
                    mma16816(acc[mt][2 * nb],     ah[mt], bl);
                    mma16816(acc[mt][2 * nb],     al[mt], bh);
                    mma16816(acc[mt][2 * nb + 1], ah[mt], bh + 2);
                    mma16816(acc[mt][2 * nb + 1], ah[mt], bl + 2);
                    mma16816(acc[mt][2 * nb + 1], al[mt], bh + 2);
                }
            }
        }
        __syncthreads();
    }

    // ---- epilogue: bias add, store, fused column stats ----
    for (int i = tid; i < NCOLS; i += 512) { csum[i] = 0.f; csq[i] = 0.f; }
    __syncthreads();

#pragma unroll
    for (int nt = 0; nt < NB * 2; ++nt) {
        int c = warp_n * WN + nt * 8 + 2 * (lane & 3);
        float2 bv = *(const float2*)&bias[c];
        float s0 = 0.f, s1 = 0.f, q0 = 0.f, q1 = 0.f;
#pragma unroll
        for (int mt = 0; mt < 2; ++mt) {
            int r0 = rowBase + warp_m * 32 + mt * 16 + (lane >> 2);
            float2 v0 = {acc[mt][nt][0] + bv.x, acc[mt][nt][1] + bv.y};
            float2 v1 = {acc[mt][nt][2] + bv.x, acc[mt][nt][3] + bv.y};
            *(float2*)&C[(size_t)r0 * NCOLS + c]       = v0;
            *(float2*)&C[(size_t)(r0 + 8) * NCOLS + c] = v1;
            s0 += v0.x + v1.x;  s1 += v0.y + v1.y;
            q0 += v0.x * v0.x + v1.x * v1.x;
            q1 += v0.y * v0.y + v1.y * v1.y;
        }
        atomicAdd(&csum[c], s0);     atomicAdd(&csum[c + 1], s1);
        atomicAdd(&csq[c],  q0);     atomicAdd(&csq[c + 1],  q1);
    }
    __syncthreads();
    for (int i = tid; i < NCOLS; i += 512) {
        atomicAdd(&stats[i],         csum[i]);
        atomicAdd(&stats[NCOLS + i], csq[i]);
    }
}

// ---- BN prep, activation, final --------------------------------------------
__global__ void bn_prep_k(const float* __restrict__ g, const float* __restrict__ be) {
    int c = threadIdx.x;
    float s  = g_stats1[c];
    float sq = g_stats1[H1N + c];
    float mean = s * (1.f / BATCH);
    float var  = sq * (1.f / BATCH) - mean * mean;
    float rstd = rsqrtf(var + BN_EPS);
    float scl  = g[c] * rstd;
    g_sc1[c] = scl;
    g_sh1[c] = be[c] - mean * scl;
}

__global__ void act_k() {
    int q = blockIdx.x * blockDim.x + threadIdx.x;
    float4 v = ((const float4*)g_H1)[q];
    int c = (q * 4) & (H1N - 1);
    float h0 = fmaxf(fmaf(v.x, g_sc1[c + 0], g_sh1[c + 0]), 0.f);
    float h1 = fmaxf(fmaf(v.y, g_sc1[c + 1], g_sh1[c + 1]), 0.f);
    float h2 = fmaxf(fmaf(v.z, g_sc1[c + 2], g_sh1[c + 2]), 0.f);
    float h3 = fmaxf(fmaf(v.w, g_sc1[c + 3], g_sh1[c + 3]), 0.f);
    __nv_bfloat162 a = __floats2bfloat162_rn(h0, h1);
    __nv_bfloat162 b = __floats2bfloat162_rn(h2, h3);
    float l0 = h0 - __bfloat162float(a.x), l1 = h1 - __bfloat162float(a.y);
    float l2 = h2 - __bfloat162float(b.x), l3 = h3 - __bfloat162float(b.y);
    __nv_bfloat162 la = __floats2bfloat162_rn(l0, l1);
    __nv_bfloat162 lb = __floats2bfloat162_rn(l2, l3);
    uint2 uh = {*(uint32_t*)&a, *(uint32_t*)&b};
    uint2 ul = {*(uint32_t*)&la, *(uint32_t*)&lb};
    ((uint2*)g_A2h)[q] = uh;
    ((uint2*)g_A2l)[q] = ul;
}

__global__ void final_k(const float* __restrict__ W3, const float* __restrict__ b3,
                        const float* __restrict__ g2, const float* __restrict__ be2,
                        float* __restrict__ out) {
    __shared__ float sc[H2N], sh[H2N], w3s[H2N];
    int tid = threadIdx.x;
    if (tid < H2N) {
        float s  = g_stats2[tid];
        float sq = g_stats2[H2N + tid];
        float mean = s * (1.f / BATCH);
        float var  = sq * (1.f / BATCH) - mean * mean;
        float rstd = rsqrtf(var + BN_EPS);
        float scl  = g2[tid] * rstd;
        sc[tid] = scl;
        sh[tid] = be2[tid] - mean * scl;
        w3s[tid] = W3[tid];
    }
    __syncthreads();
    int warp = tid >> 5, lane = tid & 31;
    int row = blockIdx.x * 8 + warp;
    float acc = 0.f;
#pragma unroll
    for (int j = 0; j < 4; ++j) {
        int c = lane + j * 32;
        float v = g_H2[(size_t)row * H2N + c];
        acc += fmaxf(fmaf(v, sc[c], sh[c]), 0.f) * w3s[c];
    }
#pragma unroll
    for (int o = 16; o; o >>= 1) acc += __shfl_xor_sync(0xffffffffu, acc, o);
    if (lane == 0) out[row] = g_fm[row] + acc + b3[0];
}

// ---------------------------------------------------------------------------
extern "C" void kernel_launch(void* const* d_in, const int* in_sizes, int n_in,
                              void* d_out, int out_size) {
    const int*   xc   = (const int*)  d_in[0];
    const float* lin  = (const float*)d_in[1];
    const float* lat  = (const float*)d_in[2];
    const float* W1   = (const float*)d_in[3];
    const float* b1   = (const float*)d_in[4];
    const float* g1   = (const float*)d_in[5];
    const float* be1  = (const float*)d_in[6];
    const float* W2   = (const float*)d_in[7];
    const float* b2   = (const float*)d_in[8];
    const float* g2   = (const float*)d_in[9];
    const float* be2  = (const float*)d_in[10];
    const float* W3   = (const float*)d_in[11];
    const float* b3   = (const float*)d_in[12];
    const float* bias = (const float*)d_in[13];
    float* out = (float*)d_out;

    unsigned short *pXh, *pXl, *pA2h, *pA2l, *pW1h, *pW1l, *pW2h, *pW2l;
    float *pH1, *pH2, *pS1, *pS2;
    cudaGetSymbolAddress((void**)&pXh,  g_Xh);
    cudaGetSymbolAddress((void**)&pXl,  g_Xl);
    cudaGetSymbolAddress((void**)&pA2h, g_A2h);
    cudaGetSymbolAddress((void**)&pA2l, g_A2l);
    cudaGetSymbolAddress((void**)&pW1h, g_W1Th);
    cudaGetSymbolAddress((void**)&pW1l, g_W1Tl);
    cudaGetSymbolAddress((void**)&pW2h, g_W2Th);
    cudaGetSymbolAddress((void**)&pW2l, g_W2Tl);
    cudaGetSymbolAddress((void**)&pH1,  g_H1);
    cudaGetSymbolAddress((void**)&pH2,  g_H2);
    cudaGetSymbolAddress((void**)&pS1,  g_stats1);
    cudaGetSymbolAddress((void**)&pS2,  g_stats2);

    // SMEM: stage = 2*TILE_A + 2*TILE_B
    constexpr int SMEM1 = 2 * (2 * 128 * 72 * 2 + 2 * H1N * 72 * 2);  // 221184
    constexpr int SMEM2 = 2 * (2 * 128 * 72 * 2 + 2 * H2N * 72 * 2);  // 147456
    cudaFuncSetAttribute(gemm_mma<DIN, H1N>,
                         cudaFuncAttributeMaxDynamicSharedMemorySize, SMEM1);
    cudaFuncSetAttribute(gemm_mma<H1N, H2N>,
                         cudaFuncAttributeMaxDynamicSharedMemorySize, SMEM2);

    zero_stats_k<<<1, 256>>>();
    prep_w_k<<<480, 256>>>(W1, W2);
    gather_fm_k<<<BATCH / 8, 256>>>(xc, lin, lat, bias);
    gemm_mma<DIN, H1N><<<BATCH / 128, 512, SMEM1>>>(
        pXh, pXl, pW1h, pW1l, b1, pH1, pS1);
    bn_prep_k<<<1, H1N>>>(g1, be1);
    act_k<<<(BATCH * H1N / 4) / 256, 256>>>();
    gemm_mma<H1N, H2N><<<BATCH / 128, 512, SMEM2>>>(
        pA2h, pA2l, pW2h, pW2l, b2, pH2, pS2);
    final_k<<<BATCH / 8, 256>>>(W3, b3, g2, be2, out);
}